// round 14
// baseline (speedup 1.0000x reference)
#include <cuda_runtime.h>
#include <cuda_bf16.h>
#include <cuda_fp16.h>
#include <cstdint>

// Problem constants
#define VOCAB 10000
#define HID   256
#define BATCH 32
#define SEQL  512
#define MTOT  (SEQL * BATCH)   // 16384
#define NCH   8                // RNN/GEMM pipeline chunks
#define TCH   (SEQL / NCH)     // 64 timesteps per chunk

typedef unsigned long long u64;

// ---------------- scratch (fp16 operands) ----------------
__device__ __half g_yh[(size_t)MTOT * HID];    // Y  [M, K] fp16
__device__ __half g_wt[(size_t)VOCAB * HID];   // Wd^T [N, K] fp16
__device__ float g_state[BATCH * HID];         // h carried between chunks

// ================= helpers =================
__device__ __forceinline__ uint32_t smem_u32(const void* p) {
    uint32_t a;
    asm("{ .reg .u64 t; cvta.to.shared.u64 t, %1; cvt.u32.u64 %0, t; }"
        : "=r"(a) : "l"(p));
    return a;
}
__device__ __forceinline__ void cpa16(uint32_t dst, const void* src, uint32_t sz) {
    asm volatile("cp.async.cg.shared.global [%0], [%1], 16, %2;"
                 :: "r"(dst), "l"(src), "r"(sz) : "memory");
}
__device__ __forceinline__ void ldm_x4(uint32_t* r, uint32_t addr) {
    asm volatile("ldmatrix.sync.aligned.m8n8.x4.shared.b16 {%0,%1,%2,%3}, [%4];"
                 : "=r"(r[0]), "=r"(r[1]), "=r"(r[2]), "=r"(r[3]) : "r"(addr));
}
__device__ __forceinline__ void mma_fp16(float* c, const uint32_t* a, const uint32_t* b) {
    asm volatile(
        "mma.sync.aligned.m16n8k16.row.col.f32.f16.f16.f32 "
        "{%0,%1,%2,%3}, {%4,%5,%6,%7}, {%8,%9}, {%0,%1,%2,%3};"
        : "+f"(c[0]), "+f"(c[1]), "+f"(c[2]), "+f"(c[3])
        : "r"(a[0]), "r"(a[1]), "r"(a[2]), "r"(a[3]), "r"(b[0]), "r"(b[1]));
}
__device__ __forceinline__ u64 packf2(float lo, float hi) {
    u64 d;
    asm("mov.b64 %0, {%1, %2};" : "=l"(d) : "f"(lo), "f"(hi));
    return d;
}
__device__ __forceinline__ void unpackf2(u64 d, float& lo, float& hi) {
    asm("mov.b64 {%0, %1}, %2;" : "=f"(lo), "=f"(hi) : "l"(d));
}
__device__ __forceinline__ u64 fma2(u64 a, u64 b, u64 c) {
    u64 d;
    asm("fma.rn.f32x2 %0, %1, %2, %3;" : "=l"(d) : "l"(a), "l"(b), "l"(c));
    return d;
}
// fast tanh: 1 - 2/(e^{2x}+1); saturates correctly at +-inf
__device__ __forceinline__ float fast_tanh(float x) {
    float z = __expf(2.0f * x);
    return 1.0f - __fdividef(2.0f, z + 1.0f);
}

// ---------------- Recurrence chunk kernel (t in [t0, t0+TCH)) ----
// 2-deep embedding prefetch (R12). Output: single fp16 Y.
#define KREG 128
#define KSH  (HID - KREG)
#define KSHQ (KSH / 4)
#define RNN_SMEM (KSHQ * HID * 16)               // 131072

__global__ void __launch_bounds__(256, 1)
rnn_kernel(const int* __restrict__ tokens, const float* __restrict__ state,
           const float* __restrict__ Wxh, const float* __restrict__ Whh,
           const float* __restrict__ bh, float* __restrict__ hfin, int t0)
{
    extern __shared__ float4 Wsh4[];                 // [KSHQ][HID] float4
    __shared__ __align__(16) float hbuf[2][HID];

    const int b = blockIdx.x;
    const int i = threadIdx.x;

    // Whh rows [0, KREG) for column i, packed as 64 f32x2 pairs
    u64 Wreg2[KREG / 2];
#pragma unroll
    for (int q = 0; q < KREG / 2; q++)
        Wreg2[q] = packf2(Whh[(2 * q) * HID + i], Whh[(2 * q + 1) * HID + i]);

    // Whh rows [KREG, 256) in shared as float4 per (kq, i)
    for (int kq = 0; kq < KSHQ; kq++) {
        float4 v;
        v.x = Whh[(KREG + 4 * kq + 0) * HID + i];
        v.y = Whh[(KREG + 4 * kq + 1) * HID + i];
        v.z = Whh[(KREG + 4 * kq + 2) * HID + i];
        v.w = Whh[(KREG + 4 * kq + 3) * HID + i];
        Wsh4[kq * HID + i] = v;
    }

    const float bias = bh[i];
    hbuf[0][i] = (t0 == 0) ? state[b * HID + i] : g_state[b * HID + i];
    __syncthreads();

    const int* toks = tokens + b * SEQL;
    float e0 = Wxh[toks[t0] * HID + i];
    float e1 = (t0 + 1 < SEQL) ? Wxh[toks[t0 + 1] * HID + i] : 0.f;
    int cur = 0;
    float hn = 0.f;

    const int tend = t0 + TCH;
    for (int t = t0; t < tend; t++) {
        // issue t+2 prefetch before the dot product
        float e2 = (t + 2 < SEQL) ? Wxh[toks[t + 2] * HID + i] : 0.f;

        u64 acc[4];
        acc[0] = packf2(e0 + bias, 0.f);
        acc[1] = 0ull; acc[2] = 0ull; acc[3] = 0ull;

        const ulonglong2* h22 = (const ulonglong2*)hbuf[cur];

#pragma unroll
        for (int q = 0; q < KREG / 4; q++) {
            ulonglong2 hv = h22[q];
            acc[0] = fma2(hv.x, Wreg2[2 * q],     acc[0]);
            acc[1] = fma2(hv.y, Wreg2[2 * q + 1], acc[1]);
        }
#pragma unroll
        for (int kq = 0; kq < KSHQ; kq++) {
            ulonglong2 hv = h22[KREG / 4 + kq];
            float4 wv = Wsh4[kq * HID + i];
            const u64* wp = (const u64*)&wv;
            acc[2] = fma2(hv.x, wp[0], acc[2]);
            acc[3] = fma2(hv.y, wp[1], acc[3]);
        }

        float s0, s1, s2, s3, s4, s5, s6, s7;
        unpackf2(acc[0], s0, s1);
        unpackf2(acc[1], s2, s3);
        unpackf2(acc[2], s4, s5);
        unpackf2(acc[3], s6, s7);
        float sum = ((s0 + s2) + (s1 + s3)) + ((s4 + s6) + (s5 + s7));

        hn = fast_tanh(sum);
        size_t oidx = ((size_t)t * BATCH + b) * HID + i;
        g_yh[oidx] = __float2half(hn);
        hbuf[cur ^ 1][i] = hn;
        __syncthreads();
        cur ^= 1;
        e0 = e1;
        e1 = e2;
    }

    // carry state to next chunk / final output
    g_state[b * HID + i] = hn;
    if (tend == SEQL) hfin[b * HID + i] = hn;
}

// ---------------- Wd transpose + fp16 convert: [K,N] f32 -> [N,K] fp16 -----
__global__ void __launch_bounds__(256)
wd_transpose_split(const float* __restrict__ Wd)
{
    __shared__ float tile[32][33];
    const int tx = threadIdx.x;          // 0..31
    const int ty = threadIdx.y;          // 0..7
    const int n0 = blockIdx.x * 32;
    const int k0 = blockIdx.y * 32;

#pragma unroll
    for (int r = 0; r < 4; r++) {
        int k = k0 + ty + r * 8;
        int n = n0 + tx;
        tile[ty + r * 8][tx] = (n < VOCAB) ? Wd[(size_t)k * VOCAB + n] : 0.f;
    }
    __syncthreads();

#pragma unroll
    for (int r = 0; r < 4; r++) {
        int n = n0 + ty + r * 8;
        int k = k0 + tx;
        if (n < VOCAB)
            g_wt[(size_t)n * HID + k] = __float2half(tile[tx][ty + r * 8]);
    }
}

// ---------------- mma.sync GEMM: C = Y @ Wt^T + bd (fp16, single pass) ------
// 128x128 CTA tile, 8 warps (2x4), 64x32 per warp, GBK=32, 2-stage cp.async.
// Stage holds 2 tiles: A (fp16 Y) and B (fp16 Wd^T).
#define GBM 128
#define GBN 128
#define GBK 32
#define ROWB 80                            // bytes per smem row (32 fp16 + pad)
#define MATB (128 * ROWB)                  // 10240 B per matrix tile
#define STAGEB (2 * MATB)                  // A, B
#define GSMEM (2 * STAGEB)                 // 40960 B

__global__ void __launch_bounds__(256, 2)
gemm_mma(const __half* __restrict__ Yv, const __half* __restrict__ Bt,
         const float* __restrict__ bd, float* __restrict__ C, int m_base)
{
    extern __shared__ __align__(16) char smraw[];
    const uint32_t base = smem_u32(smraw);

    const int tid  = threadIdx.x;
    const int lane = tid & 31;
    const int wid  = tid >> 5;
    const int wm   = wid & 1;              // 0..1
    const int wn   = wid >> 1;             // 0..3
    const int m0   = m_base + blockIdx.y * GBM;
    const int n0   = blockIdx.x * GBN;

    float acc[4][4][4];
#pragma unroll
    for (int i = 0; i < 4; i++)
#pragma unroll
        for (int j = 0; j < 4; j++)
#pragma unroll
            for (int q = 0; q < 4; q++)
                acc[i][j][q] = 0.f;

    auto load_stage = [&](int st, int kc) {
        const uint32_t sb = base + st * STAGEB;
        const int kel = kc * GBK;
#pragma unroll
        for (int j = 0; j < 2; j++) {
            int u = tid + j * 256;
            int r = u >> 2;
            int sg = u & 3;
            uint32_t off = (uint32_t)r * ROWB + sg * 16;
            cpa16(sb + off, Yv + (size_t)(m0 + r) * HID + kel + sg * 8, 16);
            int nr = n0 + r;
            uint32_t ok = (nr < VOCAB) ? 16u : 0u;
            size_t br = (nr < VOCAB) ? (size_t)nr : 0;
            cpa16(sb + MATB + off, Bt + br * HID + kel + sg * 8, ok);
        }
        asm volatile("cp.async.commit_group;" ::: "memory");
    };

    load_stage(0, 0);

    const int NKC = HID / GBK;             // 8 chunks
    for (int kc = 0; kc < NKC; kc++) {
        if (kc + 1 < NKC) {
            load_stage((kc + 1) & 1, kc + 1);
            asm volatile("cp.async.wait_group 1;" ::: "memory");
        } else {
            asm volatile("cp.async.wait_group 0;" ::: "memory");
        }
        __syncthreads();

        const uint32_t sb = base + (kc & 1) * STAGEB;
        const uint32_t Am = sb, Bm = sb + MATB;

#pragma unroll
        for (int ks = 0; ks < 2; ks++) {
            const int k0 = ks * 16;
            // B fragments: 2 x ldm.x4 (non-trans) -> 32 cols x 16 k
            uint32_t bf[2][4];
#pragma unroll
            for (int h = 0; h < 2; h++) {
                int row = wn * 32 + h * 16 + ((lane >> 4) & 1) * 8 + (lane & 7);
                int col = k0 + ((lane >> 3) & 1) * 8;
                uint32_t off = (uint32_t)row * ROWB + col * 2;
                ldm_x4(bf[h], Bm + off);
            }
#pragma unroll
            for (int mi = 0; mi < 4; mi++) {
                int rowA = wm * 64 + mi * 16 + (lane & 15);
                int colA = k0 + (lane >> 4) * 8;
                uint32_t offA = (uint32_t)rowA * ROWB + colA * 2;
                uint32_t af[4];
                ldm_x4(af, Am + offA);
#pragma unroll
                for (int ni = 0; ni < 4; ni++) {
                    const uint32_t* pb = &bf[ni >> 1][(ni & 1) * 2];
                    mma_fp16(acc[mi][ni], af, pb);
                }
            }
        }
        __syncthreads();
    }

    // ---- epilogue: bias + store ----
    const int g  = lane >> 2;
    const int tq = lane & 3;
#pragma unroll
    for (int mi = 0; mi < 4; mi++) {
        int r0 = m0 + wm * 64 + mi * 16 + g;
#pragma unroll
        for (int ni = 0; ni < 4; ni++) {
            int col = n0 + wn * 32 + ni * 8 + tq * 2;
            if (col < VOCAB) {
                float b0 = bd[col], b1 = bd[col + 1];
                float2 v0 = { acc[mi][ni][0] + b0, acc[mi][ni][1] + b1 };
                float2 v1 = { acc[mi][ni][2] + b0, acc[mi][ni][3] + b1 };
                *(float2*)(C + (size_t)r0 * VOCAB + col) = v0;
                *(float2*)(C + (size_t)(r0 + 8) * VOCAB + col) = v1;
            }
        }
    }
}

// ---------------- stream/event plumbing (created pre-main, no device allocs
// inside kernel_launch; events are timing-disabled for graph capture) -------
struct PipeResources {
    cudaStream_t s2;
    cudaEvent_t evRoot, evR[NCH], evDone;
    PipeResources() {
        cudaStreamCreateWithFlags(&s2, cudaStreamNonBlocking);
        cudaEventCreateWithFlags(&evRoot, cudaEventDisableTiming);
        for (int c = 0; c < NCH; c++)
            cudaEventCreateWithFlags(&evR[c], cudaEventDisableTiming);
        cudaEventCreateWithFlags(&evDone, cudaEventDisableTiming);
    }
};
static PipeResources g_pipe;

// ---------------- launcher: fork-join RNN/GEMM pipeline ----------------
extern "C" void kernel_launch(void* const* d_in, const int* in_sizes, int n_in,
                              void* d_out, int out_size)
{
    const int*   tokens = (const int*)  d_in[0];  // [32, 512] int32
    const float* state  = (const float*)d_in[1];  // [32, 256]
    const float* Wxh    = (const float*)d_in[2];  // [10000, 256]
    const float* Whh    = (const float*)d_in[3];  // [256, 256]
    const float* bh     = (const float*)d_in[4];  // [256]
    const float* Wd     = (const float*)d_in[5];  // [256, 10000]
    const float* bd     = (const float*)d_in[6];  // [10000]

    float* out  = (float*)d_out;                       // [16384, 10000]
    float* hfin = out + (size_t)MTOT * VOCAB;          // [32, 256]

    cudaFuncSetAttribute(rnn_kernel,
                         cudaFuncAttributeMaxDynamicSharedMemorySize, RNN_SMEM);
    cudaFuncSetAttribute(gemm_mma,
                         cudaFuncAttributeMaxDynamicSharedMemorySize, GSMEM);

    __half *yh, *wt;
    cudaGetSymbolAddress((void**)&yh, g_yh);
    cudaGetSymbolAddress((void**)&wt, g_wt);

    cudaStream_t s2 = g_pipe.s2;

    // fork: s2 joins the capture DAG off the default stream
    cudaEventRecord(g_pipe.evRoot, 0);
    cudaStreamWaitEvent(s2, g_pipe.evRoot, 0);

    // transpose (independent of RNN) on s2
    dim3 tgrid((VOCAB + 31) / 32, HID / 32);           // (313, 8)
    wd_transpose_split<<<tgrid, dim3(32, 8), 0, s2>>>(Wd);

    dim3 ggrid((VOCAB + GBN - 1) / GBN, (MTOT / NCH) / GBM);   // (79, 16)
    for (int c = 0; c < NCH; c++) {
        // RNN chunk c on default stream (serial chain)
        rnn_kernel<<<BATCH, 256, RNN_SMEM>>>(tokens, state, Wxh, Whh, bh,
                                             hfin, c * TCH);
        cudaEventRecord(g_pipe.evR[c], 0);
        // GEMM chunk c on s2, gated on RNN chunk c
        cudaStreamWaitEvent(s2, g_pipe.evR[c], 0);
        gemm_mma<<<ggrid, 256, GSMEM, s2>>>(yh, wt, bd, out,
                                            c * (MTOT / NCH));
    }

    // join: default stream waits for the GEMM stream
    cudaEventRecord(g_pipe.evDone, s2);
    cudaStreamWaitEvent(0, g_pipe.evDone, 0);
}

// round 15
// speedup vs baseline: 1.1254x; 1.1254x over previous
#include <cuda_runtime.h>
#include <cuda_bf16.h>
#include <cuda_fp16.h>
#include <cstdint>

// Problem constants
#define VOCAB 10000
#define HID   256
#define BATCH 32
#define SEQL  512
#define MTOT  (SEQL * BATCH)   // 16384
#define NCH   8                // RNN/GEMM pipeline chunks
#define TCH   (SEQL / NCH)     // 64 timesteps per chunk
#define NGS   4                // parallel GEMM streams

typedef unsigned long long u64;

// ---------------- scratch (fp16 operands) ----------------
__device__ __half g_yh[(size_t)MTOT * HID];    // Y  [M, K] fp16
__device__ __half g_wt[(size_t)VOCAB * HID];   // Wd^T [N, K] fp16
__device__ float g_state[BATCH * HID];         // h carried between chunks

// ================= helpers =================
__device__ __forceinline__ uint32_t smem_u32(const void* p) {
    uint32_t a;
    asm("{ .reg .u64 t; cvta.to.shared.u64 t, %1; cvt.u32.u64 %0, t; }"
        : "=r"(a) : "l"(p));
    return a;
}
__device__ __forceinline__ void cpa16(uint32_t dst, const void* src, uint32_t sz) {
    asm volatile("cp.async.cg.shared.global [%0], [%1], 16, %2;"
                 :: "r"(dst), "l"(src), "r"(sz) : "memory");
}
__device__ __forceinline__ void ldm_x4(uint32_t* r, uint32_t addr) {
    asm volatile("ldmatrix.sync.aligned.m8n8.x4.shared.b16 {%0,%1,%2,%3}, [%4];"
                 : "=r"(r[0]), "=r"(r[1]), "=r"(r[2]), "=r"(r[3]) : "r"(addr));
}
__device__ __forceinline__ void mma_fp16(float* c, const uint32_t* a, const uint32_t* b) {
    asm volatile(
        "mma.sync.aligned.m16n8k16.row.col.f32.f16.f16.f32 "
        "{%0,%1,%2,%3}, {%4,%5,%6,%7}, {%8,%9}, {%0,%1,%2,%3};"
        : "+f"(c[0]), "+f"(c[1]), "+f"(c[2]), "+f"(c[3])
        : "r"(a[0]), "r"(a[1]), "r"(a[2]), "r"(a[3]), "r"(b[0]), "r"(b[1]));
}
__device__ __forceinline__ u64 packf2(float lo, float hi) {
    u64 d;
    asm("mov.b64 %0, {%1, %2};" : "=l"(d) : "f"(lo), "f"(hi));
    return d;
}
__device__ __forceinline__ void unpackf2(u64 d, float& lo, float& hi) {
    asm("mov.b64 {%0, %1}, %2;" : "=f"(lo), "=f"(hi) : "l"(d));
}
__device__ __forceinline__ u64 fma2(u64 a, u64 b, u64 c) {
    u64 d;
    asm("fma.rn.f32x2 %0, %1, %2, %3;" : "=l"(d) : "l"(a), "l"(b), "l"(c));
    return d;
}
// fast tanh: 1 - 2/(e^{2x}+1); saturates correctly at +-inf
__device__ __forceinline__ float fast_tanh(float x) {
    float z = __expf(2.0f * x);
    return 1.0f - __fdividef(2.0f, z + 1.0f);
}

// ---------------- Recurrence chunk kernel (t in [t0, t0+TCH)) ----
#define KREG 128
#define KSH  (HID - KREG)
#define KSHQ (KSH / 4)
#define RNN_SMEM (KSHQ * HID * 16)               // 131072

__global__ void __launch_bounds__(256, 1)
rnn_kernel(const int* __restrict__ tokens, const float* __restrict__ state,
           const float* __restrict__ Wxh, const float* __restrict__ Whh,
           const float* __restrict__ bh, float* __restrict__ hfin, int t0)
{
    extern __shared__ float4 Wsh4[];                 // [KSHQ][HID] float4
    __shared__ __align__(16) float hbuf[2][HID];

    const int b = blockIdx.x;
    const int i = threadIdx.x;

    u64 Wreg2[KREG / 2];
#pragma unroll
    for (int q = 0; q < KREG / 2; q++)
        Wreg2[q] = packf2(Whh[(2 * q) * HID + i], Whh[(2 * q + 1) * HID + i]);

    for (int kq = 0; kq < KSHQ; kq++) {
        float4 v;
        v.x = Whh[(KREG + 4 * kq + 0) * HID + i];
        v.y = Whh[(KREG + 4 * kq + 1) * HID + i];
        v.z = Whh[(KREG + 4 * kq + 2) * HID + i];
        v.w = Whh[(KREG + 4 * kq + 3) * HID + i];
        Wsh4[kq * HID + i] = v;
    }

    const float bias = bh[i];
    hbuf[0][i] = (t0 == 0) ? state[b * HID + i] : g_state[b * HID + i];
    __syncthreads();

    const int* toks = tokens + b * SEQL;
    float e0 = Wxh[toks[t0] * HID + i];
    float e1 = (t0 + 1 < SEQL) ? Wxh[toks[t0 + 1] * HID + i] : 0.f;
    int cur = 0;
    float hn = 0.f;

    const int tend = t0 + TCH;
    for (int t = t0; t < tend; t++) {
        float e2 = (t + 2 < SEQL) ? Wxh[toks[t + 2] * HID + i] : 0.f;

        u64 acc[4];
        acc[0] = packf2(e0 + bias, 0.f);
        acc[1] = 0ull; acc[2] = 0ull; acc[3] = 0ull;

        const ulonglong2* h22 = (const ulonglong2*)hbuf[cur];

#pragma unroll
        for (int q = 0; q < KREG / 4; q++) {
            ulonglong2 hv = h22[q];
            acc[0] = fma2(hv.x, Wreg2[2 * q],     acc[0]);
            acc[1] = fma2(hv.y, Wreg2[2 * q + 1], acc[1]);
        }
#pragma unroll
        for (int kq = 0; kq < KSHQ; kq++) {
            ulonglong2 hv = h22[KREG / 4 + kq];
            float4 wv = Wsh4[kq * HID + i];
            const u64* wp = (const u64*)&wv;
            acc[2] = fma2(hv.x, wp[0], acc[2]);
            acc[3] = fma2(hv.y, wp[1], acc[3]);
        }

        float s0, s1, s2, s3, s4, s5, s6, s7;
        unpackf2(acc[0], s0, s1);
        unpackf2(acc[1], s2, s3);
        unpackf2(acc[2], s4, s5);
        unpackf2(acc[3], s6, s7);
        float sum = ((s0 + s2) + (s1 + s3)) + ((s4 + s6) + (s5 + s7));

        hn = fast_tanh(sum);
        size_t oidx = ((size_t)t * BATCH + b) * HID + i;
        g_yh[oidx] = __float2half(hn);
        hbuf[cur ^ 1][i] = hn;
        __syncthreads();
        cur ^= 1;
        e0 = e1;
        e1 = e2;
    }

    g_state[b * HID + i] = hn;
    if (tend == SEQL) hfin[b * HID + i] = hn;
}

// ---------------- Wd transpose + fp16 convert: [K,N] f32 -> [N,K] fp16 -----
__global__ void __launch_bounds__(256)
wd_transpose_split(const float* __restrict__ Wd)
{
    __shared__ float tile[32][33];
    const int tx = threadIdx.x;
    const int ty = threadIdx.y;
    const int n0 = blockIdx.x * 32;
    const int k0 = blockIdx.y * 32;

#pragma unroll
    for (int r = 0; r < 4; r++) {
        int k = k0 + ty + r * 8;
        int n = n0 + tx;
        tile[ty + r * 8][tx] = (n < VOCAB) ? Wd[(size_t)k * VOCAB + n] : 0.f;
    }
    __syncthreads();

#pragma unroll
    for (int r = 0; r < 4; r++) {
        int n = n0 + ty + r * 8;
        int k = k0 + tx;
        if (n < VOCAB)
            g_wt[(size_t)n * HID + k] = __float2half(tile[tx][ty + r * 8]);
    }
}

// ---------------- mma.sync GEMM: C = Y @ Wt^T + bd (fp16, single pass) ------
#define GBM 128
#define GBN 128
#define GBK 32
#define ROWB 80                            // bytes per smem row (32 fp16 + pad)
#define MATB (128 * ROWB)                  // 10240 B per matrix tile
#define STAGEB (2 * MATB)                  // A, B
#define GSMEM (2 * STAGEB)                 // 40960 B

__global__ void __launch_bounds__(256, 2)
gemm_mma(const __half* __restrict__ Yv, const __half* __restrict__ Bt,
         const float* __restrict__ bd, float* __restrict__ C, int m_base)
{
    extern __shared__ __align__(16) char smraw[];
    const uint32_t base = smem_u32(smraw);

    const int tid  = threadIdx.x;
    const int lane = tid & 31;
    const int wid  = tid >> 5;
    const int wm   = wid & 1;
    const int wn   = wid >> 1;
    const int m0   = m_base + blockIdx.y * GBM;
    const int n0   = blockIdx.x * GBN;

    float acc[4][4][4];
#pragma unroll
    for (int i = 0; i < 4; i++)
#pragma unroll
        for (int j = 0; j < 4; j++)
#pragma unroll
            for (int q = 0; q < 4; q++)
                acc[i][j][q] = 0.f;

    auto load_stage = [&](int st, int kc) {
        const uint32_t sb = base + st * STAGEB;
        const int kel = kc * GBK;
#pragma unroll
        for (int j = 0; j < 2; j++) {
            int u = tid + j * 256;
            int r = u >> 2;
            int sg = u & 3;
            uint32_t off = (uint32_t)r * ROWB + sg * 16;
            cpa16(sb + off, Yv + (size_t)(m0 + r) * HID + kel + sg * 8, 16);
            int nr = n0 + r;
            uint32_t ok = (nr < VOCAB) ? 16u : 0u;
            size_t br = (nr < VOCAB) ? (size_t)nr : 0;
            cpa16(sb + MATB + off, Bt + br * HID + kel + sg * 8, ok);
        }
        asm volatile("cp.async.commit_group;" ::: "memory");
    };

    load_stage(0, 0);

    const int NKC = HID / GBK;             // 8 chunks
    for (int kc = 0; kc < NKC; kc++) {
        if (kc + 1 < NKC) {
            load_stage((kc + 1) & 1, kc + 1);
            asm volatile("cp.async.wait_group 1;" ::: "memory");
        } else {
            asm volatile("cp.async.wait_group 0;" ::: "memory");
        }
        __syncthreads();

        const uint32_t sb = base + (kc & 1) * STAGEB;
        const uint32_t Am = sb, Bm = sb + MATB;

#pragma unroll
        for (int ks = 0; ks < 2; ks++) {
            const int k0 = ks * 16;
            uint32_t bf[2][4];
#pragma unroll
            for (int h = 0; h < 2; h++) {
                int row = wn * 32 + h * 16 + ((lane >> 4) & 1) * 8 + (lane & 7);
                int col = k0 + ((lane >> 3) & 1) * 8;
                uint32_t off = (uint32_t)row * ROWB + col * 2;
                ldm_x4(bf[h], Bm + off);
            }
#pragma unroll
            for (int mi = 0; mi < 4; mi++) {
                int rowA = wm * 64 + mi * 16 + (lane & 15);
                int colA = k0 + (lane >> 4) * 8;
                uint32_t offA = (uint32_t)rowA * ROWB + colA * 2;
                uint32_t af[4];
                ldm_x4(af, Am + offA);
#pragma unroll
                for (int ni = 0; ni < 4; ni++) {
                    const uint32_t* pb = &bf[ni >> 1][(ni & 1) * 2];
                    mma_fp16(acc[mi][ni], af, pb);
                }
            }
        }
        __syncthreads();
    }

    // ---- epilogue: bias + store ----
    const int g  = lane >> 2;
    const int tq = lane & 3;
#pragma unroll
    for (int mi = 0; mi < 4; mi++) {
        int r0 = m0 + wm * 64 + mi * 16 + g;
#pragma unroll
        for (int ni = 0; ni < 4; ni++) {
            int col = n0 + wn * 32 + ni * 8 + tq * 2;
            if (col < VOCAB) {
                float b0 = bd[col], b1 = bd[col + 1];
                float2 v0 = { acc[mi][ni][0] + b0, acc[mi][ni][1] + b1 };
                float2 v1 = { acc[mi][ni][2] + b0, acc[mi][ni][3] + b1 };
                *(float2*)(C + (size_t)r0 * VOCAB + col) = v0;
                *(float2*)(C + (size_t)(r0 + 8) * VOCAB + col) = v1;
            }
        }
    }
}

// ---------------- stream/event plumbing (created pre-main; capture-safe) ----
struct PipeResources {
    cudaStream_t sg[NGS];
    cudaEvent_t evRoot, evT, evR[NCH], evG[NGS];
    PipeResources() {
        for (int i = 0; i < NGS; i++)
            cudaStreamCreateWithFlags(&sg[i], cudaStreamNonBlocking);
        cudaEventCreateWithFlags(&evRoot, cudaEventDisableTiming);
        cudaEventCreateWithFlags(&evT, cudaEventDisableTiming);
        for (int c = 0; c < NCH; c++)
            cudaEventCreateWithFlags(&evR[c], cudaEventDisableTiming);
        for (int i = 0; i < NGS; i++)
            cudaEventCreateWithFlags(&evG[i], cudaEventDisableTiming);
    }
};
static PipeResources g_pipe;

// ---------------- launcher: RNN chain + 4-way parallel GEMM chunks ----------
extern "C" void kernel_launch(void* const* d_in, const int* in_sizes, int n_in,
                              void* d_out, int out_size)
{
    const int*   tokens = (const int*)  d_in[0];  // [32, 512] int32
    const float* state  = (const float*)d_in[1];  // [32, 256]
    const float* Wxh    = (const float*)d_in[2];  // [10000, 256]
    const float* Whh    = (const float*)d_in[3];  // [256, 256]
    const float* bh     = (const float*)d_in[4];  // [256]
    const float* Wd     = (const float*)d_in[5];  // [256, 10000]
    const float* bd     = (const float*)d_in[6];  // [10000]

    float* out  = (float*)d_out;                       // [16384, 10000]
    float* hfin = out + (size_t)MTOT * VOCAB;          // [32, 256]

    cudaFuncSetAttribute(rnn_kernel,
                         cudaFuncAttributeMaxDynamicSharedMemorySize, RNN_SMEM);
    cudaFuncSetAttribute(gemm_mma,
                         cudaFuncAttributeMaxDynamicSharedMemorySize, GSMEM);

    __half *yh, *wt;
    cudaGetSymbolAddress((void**)&yh, g_yh);
    cudaGetSymbolAddress((void**)&wt, g_wt);

    // fork all GEMM streams off the default stream
    cudaEventRecord(g_pipe.evRoot, 0);
    for (int i = 0; i < NGS; i++)
        cudaStreamWaitEvent(g_pipe.sg[i], g_pipe.evRoot, 0);

    // transpose on sg[0]; all other gemm streams gate on it
    dim3 tgrid((VOCAB + 31) / 32, HID / 32);           // (313, 8)
    wd_transpose_split<<<tgrid, dim3(32, 8), 0, g_pipe.sg[0]>>>(Wd);
    cudaEventRecord(g_pipe.evT, g_pipe.sg[0]);
    for (int i = 1; i < NGS; i++)
        cudaStreamWaitEvent(g_pipe.sg[i], g_pipe.evT, 0);

    dim3 ggrid((VOCAB + GBN - 1) / GBN, (MTOT / NCH) / GBM);   // (79, 16)
    for (int c = 0; c < NCH; c++) {
        // RNN chunk c on default stream (serial chain)
        rnn_kernel<<<BATCH, 256, RNN_SMEM>>>(tokens, state, Wxh, Whh, bh,
                                             hfin, c * TCH);
        cudaEventRecord(g_pipe.evR[c], 0);
        // GEMM chunk c on stream c%NGS, gated on RNN chunk c
        cudaStream_t s = g_pipe.sg[c % NGS];
        cudaStreamWaitEvent(s, g_pipe.evR[c], 0);
        gemm_mma<<<ggrid, 256, GSMEM, s>>>(yh, wt, bd, out,
                                           c * (MTOT / NCH));
    }

    // join: default stream waits for all GEMM streams
    for (int i = 0; i < NGS; i++) {
        cudaEventRecord(g_pipe.evG[i], g_pipe.sg[i]);
        cudaStreamWaitEvent(0, g_pipe.evG[i], 0);
    }
}